// round 13
// baseline (speedup 1.0000x reference)
#include <cuda_runtime.h>
#include <cuda_fp16.h>
#include <math.h>
#include <cstdint>

// ---------------------------------------------------------------------------
// Problem constants
// ---------------------------------------------------------------------------
#define Bsz   4096
#define Hh    1024
#define FourH 4096
#define Ktot  2048

// GEMM tiling (R4 measured-best): CTA 128x128, warp 32x64, BK=32, 4-stage
#define BM 128
#define BN 128
#define BK 32
#define NKITERS (Ktot / BK)        // 64
#define GTHREADS 256
#define NSTAGES 4

// SMEM strides (bytes) — padded for conflict-free ldmatrix
#define A_STRIDE 80                 // 64B data + 16B pad
#define B_STRIDE 272                // 256B data + 16B pad
#define A_TILE_BYTES (BM * A_STRIDE)        // 10240
#define B_TILE_BYTES (BK * B_STRIDE)        // 8704
#define OFF_A  0
#define OFF_B  A_TILE_BYTES
#define STAGE_BYTES (A_TILE_BYTES + B_TILE_BYTES)   // 18944
#define SMEM_TOTAL (NSTAGES * STAGE_BYTES)          // 75776

// ---------------------------------------------------------------------------
// Device scratch
// ---------------------------------------------------------------------------
__device__ __half g_af[(size_t)Bsz * FourH];     // fp16 pre-activations (32 MB)
__device__ __half g_Ah[(size_t)Bsz * Ktot];      // A fp16 [4096][2048]
__device__ __half g_B [(size_t)Ktot * FourH];    // W fp16 [2048][4096]

// ---------------------------------------------------------------------------
// PTX helpers
// ---------------------------------------------------------------------------
__device__ __forceinline__ uint32_t smem_u32(const void* p) {
    uint32_t a;
    asm("{ .reg .u64 t; cvta.to.shared.u64 t, %1; cvt.u32.u64 %0, t; }" : "=r"(a) : "l"(p));
    return a;
}
__device__ __forceinline__ void cp16(uint32_t smem_addr, const void* gptr) {
    asm volatile("cp.async.cg.shared.global [%0], [%1], 16;" :: "r"(smem_addr), "l"(gptr));
}
#define CP_COMMIT() asm volatile("cp.async.commit_group;" ::: "memory")
#define CP_WAIT(n)  asm volatile("cp.async.wait_group %0;" :: "n"(n) : "memory")

#define LDSM_X4(r0,r1,r2,r3, addr) \
    asm volatile("ldmatrix.sync.aligned.m8n8.x4.shared.b16 {%0,%1,%2,%3}, [%4];" \
                 : "=r"(r0), "=r"(r1), "=r"(r2), "=r"(r3) : "r"(addr))
#define LDSM_X4_T(r0,r1,r2,r3, addr) \
    asm volatile("ldmatrix.sync.aligned.m8n8.x4.trans.shared.b16 {%0,%1,%2,%3}, [%4];" \
                 : "=r"(r0), "=r"(r1), "=r"(r2), "=r"(r3) : "r"(addr))

__device__ __forceinline__ void mma16816(float* c, const uint32_t* a, const uint32_t* b) {
    asm volatile(
        "mma.sync.aligned.m16n8k16.row.col.f32.f16.f16.f32 "
        "{%0,%1,%2,%3}, {%4,%5,%6,%7}, {%8,%9}, {%0,%1,%2,%3};"
        : "+f"(c[0]), "+f"(c[1]), "+f"(c[2]), "+f"(c[3])
        : "r"(a[0]), "r"(a[1]), "r"(a[2]), "r"(a[3]), "r"(b[0]), "r"(b[1]));
}

// ---------------------------------------------------------------------------
// Merged convert: one launch converts A = [x|prev_h] and B = [Wx;Wh] to fp16.
// 8 floats per thread; __ldcs on one-shot fp32 reads.
// ---------------------------------------------------------------------------
#define A_GROUPS (Bsz * Ktot / 8)       // 1M
#define B_GROUPS (Ktot * FourH / 8)     // 1M

__global__ __launch_bounds__(256)
void convert_all_kernel(const float* __restrict__ x,  const float* __restrict__ ph,
                        const float* __restrict__ Wx, const float* __restrict__ Wh) {
    const int idx = blockIdx.x * 256 + threadIdx.x;
    const float* src;
    __half* dst;
    if (idx < A_GROUPS) {
        const int row = idx >> 8;                   // 2048/8 = 256 groups/row
        const int col = (idx & 255) * 8;
        src = (col < 1024) ? (x + (size_t)row * 1024 + col)
                           : (ph + (size_t)row * 1024 + (col - 1024));
        dst = g_Ah + (size_t)row * Ktot + col;
    } else {
        const int bi  = idx - A_GROUPS;
        const int row = bi >> 9;                    // 4096/8 = 512 groups/row
        const int col = (bi & 511) * 8;
        src = (row < 1024) ? (Wx + (size_t)row * FourH + col)
                           : (Wh + (size_t)(row - 1024) * FourH + col);
        dst = g_B + (size_t)row * FourH + col;
    }
    const float4 v0 = __ldcs((const float4*)src);
    const float4 v1 = __ldcs((const float4*)src + 1);
    __half2 h[4];
    h[0] = __floats2half2_rn(v0.x, v0.y);
    h[1] = __floats2half2_rn(v0.z, v0.w);
    h[2] = __floats2half2_rn(v1.x, v1.y);
    h[3] = __floats2half2_rn(v1.z, v1.w);
    *(uint4*)dst = *(const uint4*)h;
}

// ---------------------------------------------------------------------------
// Tensor-core GEMM: g_af = fp16(A @ B + bias)
// R4 loop order (wait -> sync -> compute -> sync -> load), BK=32, 4 stages.
// ---------------------------------------------------------------------------
__global__ __launch_bounds__(GTHREADS, 2)
void gemm_mma_kernel(const float* __restrict__ bias) {
    extern __shared__ char smem[];
    const uint32_t sbase = smem_u32(smem);
    const int tid  = threadIdx.x;
    const int warp = tid >> 5;
    const int lid  = tid & 31;

    const int mBase = blockIdx.y * BM;
    const int nBase = blockIdx.x * BN;

    const int warpM = warp & 3;
    const int warpN = warp >> 2;
    const int wm = warpM * 32;
    const int wn = warpN * 64;

    const int aRowInTile = (lid & 7) + ((lid >> 3) & 1) * 8;   // 0..15
    const int aKoff      = (lid >> 4) * 8;                     // 0 or 8
    const int bKInTile   = (lid & 7) + ((lid >> 3) & 1) * 8;   // 0..15
    const int bNoff      = (lid >> 4) * 8;                     // 0 or 8

    float acc[2][8][4];
    #pragma unroll
    for (int mt = 0; mt < 2; ++mt)
        #pragma unroll
        for (int nt = 0; nt < 8; ++nt)
            #pragma unroll
            for (int q = 0; q < 4; ++q) acc[mt][nt][q] = 0.0f;

    auto load_stage = [&](int kc, int s) {
        const uint32_t st = sbase + (uint32_t)s * STAGE_BYTES;
        const int kB = kc * BK;
        // A: 128 rows x 64B = 512 16B-chunks, 2 per thread
        #pragma unroll
        for (int i = 0; i < 2; ++i) {
            const int u   = tid + i * 256;
            const int row = u >> 2;
            const int c4  = u & 3;
            cp16(st + OFF_A + (uint32_t)(row * A_STRIDE + c4 * 16),
                 g_Ah + (size_t)(mBase + row) * Ktot + kB + c4 * 8);
        }
        // B: 32 rows x 256B = 512 16B-chunks, 2 per thread
        #pragma unroll
        for (int i = 0; i < 2; ++i) {
            const int u   = tid + i * 256;
            const int row = u >> 4;
            const int c16 = u & 15;
            cp16(st + OFF_B + (uint32_t)(row * B_STRIDE + c16 * 16),
                 g_B + (size_t)(kB + row) * FourH + nBase + c16 * 8);
        }
        CP_COMMIT();
    };

    load_stage(0, 0);
    load_stage(1, 1);
    load_stage(2, 2);
    load_stage(3, 3);

    #pragma unroll 1
    for (int kc = 0; kc < NKITERS; ++kc) {
        const int s = kc & (NSTAGES - 1);
        // wait until tile kc's group has completed (allow the rest in flight)
        if      (kc < NKITERS - 3)  { CP_WAIT(3); }
        else if (kc == NKITERS - 3) { CP_WAIT(2); }
        else if (kc == NKITERS - 2) { CP_WAIT(1); }
        else                        { CP_WAIT(0); }
        __syncthreads();

        const uint32_t st = sbase + (uint32_t)s * STAGE_BYTES;

        #pragma unroll
        for (int kk = 0; kk < BK; kk += 16) {
            uint32_t af[2][4];
            #pragma unroll
            for (int mt = 0; mt < 2; ++mt) {
                const uint32_t ra = (uint32_t)((wm + mt * 16 + aRowInTile) * A_STRIDE
                                               + (kk + aKoff) * 2);
                LDSM_X4(af[mt][0], af[mt][1], af[mt][2], af[mt][3], st + OFF_A + ra);
            }
            uint32_t bf[8][2];
            #pragma unroll
            for (int np = 0; np < 4; ++np) {
                const uint32_t rb = (uint32_t)((kk + bKInTile) * B_STRIDE
                                               + (wn + np * 16 + bNoff) * 2);
                uint32_t r0, r1, r2, r3;
                LDSM_X4_T(r0, r1, r2, r3, st + OFF_B + rb);
                bf[np * 2][0] = r0;     bf[np * 2][1] = r1;
                bf[np * 2 + 1][0] = r2; bf[np * 2 + 1][1] = r3;
            }
            #pragma unroll
            for (int mt = 0; mt < 2; ++mt)
                #pragma unroll
                for (int nt = 0; nt < 8; ++nt)
                    mma16816(acc[mt][nt], af[mt], bf[nt]);
        }
        __syncthreads();
        if (kc + NSTAGES < NKITERS) load_stage(kc + NSTAGES, s);
    }

    // ---- epilogue: fp16(acc + bias) -> g_af ----
    const int tr = lid >> 2;
    const int tc = (lid & 3) * 2;
    #pragma unroll
    for (int mt = 0; mt < 2; ++mt) {
        #pragma unroll
        for (int nt = 0; nt < 8; ++nt) {
            const int r0 = mBase + wm + mt * 16 + tr;
            const int c  = nBase + wn + nt * 8 + tc;
            const float b0 = __ldg(bias + c);
            const float b1 = __ldg(bias + c + 1);
            *(__half2*)(g_af + (size_t)r0 * FourH + c) =
                __floats2half2_rn(acc[mt][nt][0] + b0, acc[mt][nt][1] + b1);
            *(__half2*)(g_af + (size_t)(r0 + 8) * FourH + c) =
                __floats2half2_rn(acc[mt][nt][2] + b0, acc[mt][nt][3] + b1);
        }
    }
}

// ---------------------------------------------------------------------------
// LayerNorm + gates + cell update (fast-math MUFU gates)
// ---------------------------------------------------------------------------
__device__ __forceinline__ float fast_sigmoid(float v) {
    return __fdividef(1.0f, 1.0f + __expf(-v));
}
__device__ __forceinline__ float fast_tanh(float v) {
    return __fdividef(2.0f, 1.0f + __expf(-2.0f * v)) - 1.0f;
}

__global__ __launch_bounds__(256)
void ln_gates_kernel(const float* __restrict__ prev_c,
                     const float* __restrict__ gamma,
                     const float* __restrict__ beta,
                     float* __restrict__ next_h,
                     float* __restrict__ next_c)
{
    const int row = blockIdx.x;
    const int tid = threadIdx.x;
    const int j   = tid * 4;
    const __half* ar = g_af + (size_t)row * FourH;

    float4 v[4];
    #pragma unroll
    for (int s = 0; s < 4; ++s) {
        const uint2 raw = *(const uint2*)(ar + s * Hh + j);
        const float2 lo = __half22float2(*(const __half2*)&raw.x);
        const float2 hi = __half22float2(*(const __half2*)&raw.y);
        v[s] = make_float4(lo.x, lo.y, hi.x, hi.y);
    }

    float sum = 0.0f, sq = 0.0f;
    #pragma unroll
    for (int s = 0; s < 4; ++s) {
        sum += v[s].x + v[s].y + v[s].z + v[s].w;
        sq  += v[s].x * v[s].x + v[s].y * v[s].y + v[s].z * v[s].z + v[s].w * v[s].w;
    }
    #pragma unroll
    for (int off = 16; off > 0; off >>= 1) {
        sum += __shfl_xor_sync(0xffffffffu, sum, off);
        sq  += __shfl_xor_sync(0xffffffffu, sq,  off);
    }
    __shared__ float red_sum[8], red_sq[8];
    const int warp = tid >> 5;
    if ((tid & 31) == 0) { red_sum[warp] = sum; red_sq[warp] = sq; }
    __syncthreads();
    float tsum = 0.0f, tsq = 0.0f;
    #pragma unroll
    for (int w = 0; w < 8; ++w) { tsum += red_sum[w]; tsq += red_sq[w]; }

    const float inv_n = 1.0f / (float)FourH;
    const float mu   = tsum * inv_n;
    const float var  = tsq * inv_n - mu * mu;
    const float rstd = rsqrtf(var + 1e-5f);

    float n[4][4];
    #pragma unroll
    for (int s = 0; s < 4; ++s) {
        const float4 gm = *(const float4*)(gamma + s * Hh + j);
        const float4 bt = *(const float4*)(beta  + s * Hh + j);
        n[s][0] = (v[s].x - mu) * rstd * gm.x + bt.x;
        n[s][1] = (v[s].y - mu) * rstd * gm.y + bt.y;
        n[s][2] = (v[s].z - mu) * rstd * gm.z + bt.z;
        n[s][3] = (v[s].w - mu) * rstd * gm.w + bt.w;
    }

    const float4 pc = *(const float4*)(prev_c + (size_t)row * Hh + j);
    const float pcv[4] = {pc.x, pc.y, pc.z, pc.w};

    float4 hc, cc;
    float* hp = &hc.x;
    float* cp = &cc.x;
    #pragma unroll
    for (int c = 0; c < 4; ++c) {
        const float ig = fast_sigmoid(n[0][c]);
        const float fg = fast_sigmoid(n[1][c]);
        const float og = fast_sigmoid(n[2][c]);
        const float gg = fast_tanh(n[3][c]);
        const float cn = fg * pcv[c] + ig * gg;
        cp[c] = cn;
        hp[c] = og * fast_tanh(cn);
    }
    *(float4*)(next_h + (size_t)row * Hh + j) = hc;
    *(float4*)(next_c + (size_t)row * Hh + j) = cc;
}

// ---------------------------------------------------------------------------
// Launch
// ---------------------------------------------------------------------------
extern "C" void kernel_launch(void* const* d_in, const int* in_sizes, int n_in,
                              void* d_out, int out_size)
{
    const float* x     = (const float*)d_in[0];
    const float* ph    = (const float*)d_in[1];
    const float* pc    = (const float*)d_in[2];
    const float* Wx    = (const float*)d_in[3];
    const float* Wh    = (const float*)d_in[4];
    const float* bias  = (const float*)d_in[5];
    const float* gamma = (const float*)d_in[6];
    const float* beta  = (const float*)d_in[7];

    float* out    = (float*)d_out;
    float* next_h = out;
    float* next_c = out + (size_t)out_size / 2;

    convert_all_kernel<<<(A_GROUPS + B_GROUPS) / 256, 256>>>(x, ph, Wx, Wh);

    cudaFuncSetAttribute(gemm_mma_kernel,
                         cudaFuncAttributeMaxDynamicSharedMemorySize, SMEM_TOTAL);
    gemm_mma_kernel<<<dim3(FourH / BN, Bsz / BM), GTHREADS, SMEM_TOTAL>>>(bias);

    ln_gates_kernel<<<Bsz, 256>>>(pc, gamma, beta, next_h, next_c);
}

// round 15
// speedup vs baseline: 1.0562x; 1.0562x over previous
#include <cuda_runtime.h>
#include <cuda_fp16.h>
#include <math.h>
#include <cstdint>

// ---------------------------------------------------------------------------
// Problem constants
// ---------------------------------------------------------------------------
#define Bsz   4096
#define Hh    1024
#define FourH 4096
#define Ktot  2048

// GEMM tiling (R10 measured-best): CTA 128x128, warp 32x64, BK=64, 2-stage
#define BM 128
#define BN 128
#define BK 64
#define NKITERS (Ktot / BK)        // 32
#define GTHREADS 256
#define NSTAGES 2

// SMEM strides (bytes) — padded for conflict-free ldmatrix
#define A_STRIDE 144                // 128B data + 16B pad (9 x 16B, odd)
#define B_STRIDE 272                // 256B data + 16B pad (17 x 16B, odd)
#define A_TILE_BYTES (BM * A_STRIDE)        // 18432
#define B_TILE_BYTES (BK * B_STRIDE)        // 17408
#define OFF_A  0
#define OFF_B  A_TILE_BYTES
#define STAGE_BYTES (A_TILE_BYTES + B_TILE_BYTES)   // 35840
#define SMEM_TOTAL (NSTAGES * STAGE_BYTES)          // 71680

// ---------------------------------------------------------------------------
// Device scratch
// ---------------------------------------------------------------------------
__device__ __half g_af[(size_t)Bsz * FourH];     // fp16 pre-activations (32 MB)
__device__ __half g_Ah[(size_t)Bsz * Ktot];      // A fp16 [4096][2048]
__device__ __half g_B [(size_t)Ktot * FourH];    // W fp16 [2048][4096]

// ---------------------------------------------------------------------------
// PTX helpers
// ---------------------------------------------------------------------------
__device__ __forceinline__ uint32_t smem_u32(const void* p) {
    uint32_t a;
    asm("{ .reg .u64 t; cvta.to.shared.u64 t, %1; cvt.u32.u64 %0, t; }" : "=r"(a) : "l"(p));
    return a;
}
__device__ __forceinline__ void cp16(uint32_t smem_addr, const void* gptr) {
    asm volatile("cp.async.cg.shared.global [%0], [%1], 16;" :: "r"(smem_addr), "l"(gptr));
}
#define CP_COMMIT() asm volatile("cp.async.commit_group;" ::: "memory")
#define CP_WAIT(n)  asm volatile("cp.async.wait_group %0;" :: "n"(n) : "memory")

#define LDSM_X4(r0,r1,r2,r3, addr) \
    asm volatile("ldmatrix.sync.aligned.m8n8.x4.shared.b16 {%0,%1,%2,%3}, [%4];" \
                 : "=r"(r0), "=r"(r1), "=r"(r2), "=r"(r3) : "r"(addr))
#define LDSM_X4_T(r0,r1,r2,r3, addr) \
    asm volatile("ldmatrix.sync.aligned.m8n8.x4.trans.shared.b16 {%0,%1,%2,%3}, [%4];" \
                 : "=r"(r0), "=r"(r1), "=r"(r2), "=r"(r3) : "r"(addr))

__device__ __forceinline__ void mma16816(float* c, const uint32_t* a, const uint32_t* b) {
    asm volatile(
        "mma.sync.aligned.m16n8k16.row.col.f32.f16.f16.f32 "
        "{%0,%1,%2,%3}, {%4,%5,%6,%7}, {%8,%9}, {%0,%1,%2,%3};"
        : "+f"(c[0]), "+f"(c[1]), "+f"(c[2]), "+f"(c[3])
        : "r"(a[0]), "r"(a[1]), "r"(a[2]), "r"(a[3]), "r"(b[0]), "r"(b[1]));
}

// ---------------------------------------------------------------------------
// Merged convert (R13 measured: 14.9us): A = [x|prev_h] and B = [Wx;Wh] -> fp16
// ---------------------------------------------------------------------------
#define A_GROUPS (Bsz * Ktot / 8)       // 1M
#define B_GROUPS (Ktot * FourH / 8)     // 1M

__global__ __launch_bounds__(256)
void convert_all_kernel(const float* __restrict__ x,  const float* __restrict__ ph,
                        const float* __restrict__ Wx, const float* __restrict__ Wh) {
    const int idx = blockIdx.x * 256 + threadIdx.x;
    const float* src;
    __half* dst;
    if (idx < A_GROUPS) {
        const int row = idx >> 8;                   // 2048/8 = 256 groups/row
        const int col = (idx & 255) * 8;
        src = (col < 1024) ? (x + (size_t)row * 1024 + col)
                           : (ph + (size_t)row * 1024 + (col - 1024));
        dst = g_Ah + (size_t)row * Ktot + col;
    } else {
        const int bi  = idx - A_GROUPS;
        const int row = bi >> 9;                    // 4096/8 = 512 groups/row
        const int col = (bi & 511) * 8;
        src = (row < 1024) ? (Wx + (size_t)row * FourH + col)
                           : (Wh + (size_t)(row - 1024) * FourH + col);
        dst = g_B + (size_t)row * FourH + col;
    }
    const float4 v0 = __ldcs((const float4*)src);
    const float4 v1 = __ldcs((const float4*)src + 1);
    __half2 h[4];
    h[0] = __floats2half2_rn(v0.x, v0.y);
    h[1] = __floats2half2_rn(v0.z, v0.w);
    h[2] = __floats2half2_rn(v1.x, v1.y);
    h[3] = __floats2half2_rn(v1.z, v1.w);
    *(uint4*)dst = *(const uint4*)h;
}

// ---------------------------------------------------------------------------
// Tensor-core GEMM (exact R10 measured-best): g_af = fp16(A @ B + bias)
// BK=64, 2-stage, wait -> sync -> compute -> sync -> load.
// ---------------------------------------------------------------------------
__global__ __launch_bounds__(GTHREADS, 2)
void gemm_mma_kernel(const float* __restrict__ bias) {
    extern __shared__ char smem[];
    const uint32_t sbase = smem_u32(smem);
    const int tid  = threadIdx.x;
    const int warp = tid >> 5;
    const int lid  = tid & 31;

    const int mBase = blockIdx.y * BM;
    const int nBase = blockIdx.x * BN;

    const int warpM = warp & 3;
    const int warpN = warp >> 2;
    const int wm = warpM * 32;
    const int wn = warpN * 64;

    const int aRowInTile = (lid & 7) + ((lid >> 3) & 1) * 8;   // 0..15
    const int aKoff      = (lid >> 4) * 8;                     // 0 or 8
    const int bKInTile   = (lid & 7) + ((lid >> 3) & 1) * 8;   // 0..15
    const int bNoff      = (lid >> 4) * 8;                     // 0 or 8

    float acc[2][8][4];
    #pragma unroll
    for (int mt = 0; mt < 2; ++mt)
        #pragma unroll
        for (int nt = 0; nt < 8; ++nt)
            #pragma unroll
            for (int q = 0; q < 4; ++q) acc[mt][nt][q] = 0.0f;

    auto load_stage = [&](int kc, int s) {
        const uint32_t st = sbase + (uint32_t)s * STAGE_BYTES;
        const int kB = kc * BK;
        // A: 128 rows x 128B = 1024 16B-chunks, 4 per thread
        #pragma unroll
        for (int i = 0; i < 4; ++i) {
            const int u   = tid + i * 256;
            const int row = u >> 3;
            const int c8  = u & 7;
            cp16(st + OFF_A + (uint32_t)(row * A_STRIDE + c8 * 16),
                 g_Ah + (size_t)(mBase + row) * Ktot + kB + c8 * 8);
        }
        // B: 64 rows x 256B = 1024 16B-chunks, 4 per thread
        #pragma unroll
        for (int i = 0; i < 4; ++i) {
            const int u   = tid + i * 256;
            const int row = u >> 4;
            const int c16 = u & 15;
            cp16(st + OFF_B + (uint32_t)(row * B_STRIDE + c16 * 16),
                 g_B + (size_t)(kB + row) * FourH + nBase + c16 * 8);
        }
        CP_COMMIT();
    };

    load_stage(0, 0);
    load_stage(1, 1);

    #pragma unroll 1
    for (int kc = 0; kc < NKITERS; ++kc) {
        const int s = kc & 1;
        if (kc < NKITERS - 1) { CP_WAIT(1); } else { CP_WAIT(0); }
        __syncthreads();

        const uint32_t st = sbase + (uint32_t)s * STAGE_BYTES;

        #pragma unroll
        for (int kk = 0; kk < BK; kk += 16) {
            uint32_t af[2][4];
            #pragma unroll
            for (int mt = 0; mt < 2; ++mt) {
                const uint32_t ra = (uint32_t)((wm + mt * 16 + aRowInTile) * A_STRIDE
                                               + (kk + aKoff) * 2);
                LDSM_X4(af[mt][0], af[mt][1], af[mt][2], af[mt][3], st + OFF_A + ra);
            }
            uint32_t bf[8][2];
            #pragma unroll
            for (int np = 0; np < 4; ++np) {
                const uint32_t rb = (uint32_t)((kk + bKInTile) * B_STRIDE
                                               + (wn + np * 16 + bNoff) * 2);
                uint32_t r0, r1, r2, r3;
                LDSM_X4_T(r0, r1, r2, r3, st + OFF_B + rb);
                bf[np * 2][0] = r0;     bf[np * 2][1] = r1;
                bf[np * 2 + 1][0] = r2; bf[np * 2 + 1][1] = r3;
            }
            #pragma unroll
            for (int mt = 0; mt < 2; ++mt)
                #pragma unroll
                for (int nt = 0; nt < 8; ++nt)
                    mma16816(acc[mt][nt], af[mt], bf[nt]);
        }
        __syncthreads();
        if (kc + NSTAGES < NKITERS) load_stage(kc + NSTAGES, s);
    }

    // ---- epilogue: fp16(acc + bias) -> g_af ----
    const int tr = lid >> 2;
    const int tc = (lid & 3) * 2;
    #pragma unroll
    for (int mt = 0; mt < 2; ++mt) {
        #pragma unroll
        for (int nt = 0; nt < 8; ++nt) {
            const int r0 = mBase + wm + mt * 16 + tr;
            const int c  = nBase + wn + nt * 8 + tc;
            const float b0 = __ldg(bias + c);
            const float b1 = __ldg(bias + c + 1);
            *(__half2*)(g_af + (size_t)r0 * FourH + c) =
                __floats2half2_rn(acc[mt][nt][0] + b0, acc[mt][nt][1] + b1);
            *(__half2*)(g_af + (size_t)(r0 + 8) * FourH + c) =
                __floats2half2_rn(acc[mt][nt][2] + b0, acc[mt][nt][3] + b1);
        }
    }
}

// ---------------------------------------------------------------------------
// LayerNorm + gates + cell update (fast-math MUFU gates; R10 measured 20.3us)
// ---------------------------------------------------------------------------
__device__ __forceinline__ float fast_sigmoid(float v) {
    return __fdividef(1.0f, 1.0f + __expf(-v));
}
__device__ __forceinline__ float fast_tanh(float v) {
    return __fdividef(2.0f, 1.0f + __expf(-2.0f * v)) - 1.0f;
}

__global__ __launch_bounds__(256)
void ln_gates_kernel(const float* __restrict__ prev_c,
                     const float* __restrict__ gamma,
                     const float* __restrict__ beta,
                     float* __restrict__ next_h,
                     float* __restrict__ next_c)
{
    const int row = blockIdx.x;
    const int tid = threadIdx.x;
    const int j   = tid * 4;
    const __half* ar = g_af + (size_t)row * FourH;

    float4 v[4];
    #pragma unroll
    for (int s = 0; s < 4; ++s) {
        const uint2 raw = *(const uint2*)(ar + s * Hh + j);
        const float2 lo = __half22float2(*(const __half2*)&raw.x);
        const float2 hi = __half22float2(*(const __half2*)&raw.y);
        v[s] = make_float4(lo.x, lo.y, hi.x, hi.y);
    }

    float sum = 0.0f, sq = 0.0f;
    #pragma unroll
    for (int s = 0; s < 4; ++s) {
        sum += v[s].x + v[s].y + v[s].z + v[s].w;
        sq  += v[s].x * v[s].x + v[s].y * v[s].y + v[s].z * v[s].z + v[s].w * v[s].w;
    }
    #pragma unroll
    for (int off = 16; off > 0; off >>= 1) {
        sum += __shfl_xor_sync(0xffffffffu, sum, off);
        sq  += __shfl_xor_sync(0xffffffffu, sq,  off);
    }
    __shared__ float red_sum[8], red_sq[8];
    const int warp = tid >> 5;
    if ((tid & 31) == 0) { red_sum[warp] = sum; red_sq[warp] = sq; }
    __syncthreads();
    float tsum = 0.0f, tsq = 0.0f;
    #pragma unroll
    for (int w = 0; w < 8; ++w) { tsum += red_sum[w]; tsq += red_sq[w]; }

    const float inv_n = 1.0f / (float)FourH;
    const float mu   = tsum * inv_n;
    const float var  = tsq * inv_n - mu * mu;
    const float rstd = rsqrtf(var + 1e-5f);

    float n[4][4];
    #pragma unroll
    for (int s = 0; s < 4; ++s) {
        const float4 gm = *(const float4*)(gamma + s * Hh + j);
        const float4 bt = *(const float4*)(beta  + s * Hh + j);
        n[s][0] = (v[s].x - mu) * rstd * gm.x + bt.x;
        n[s][1] = (v[s].y - mu) * rstd * gm.y + bt.y;
        n[s][2] = (v[s].z - mu) * rstd * gm.z + bt.z;
        n[s][3] = (v[s].w - mu) * rstd * gm.w + bt.w;
    }

    const float4 pc = *(const float4*)(prev_c + (size_t)row * Hh + j);
    const float pcv[4] = {pc.x, pc.y, pc.z, pc.w};

    float4 hc, cc;
    float* hp = &hc.x;
    float* cp = &cc.x;
    #pragma unroll
    for (int c = 0; c < 4; ++c) {
        const float ig = fast_sigmoid(n[0][c]);
        const float fg = fast_sigmoid(n[1][c]);
        const float og = fast_sigmoid(n[2][c]);
        const float gg = fast_tanh(n[3][c]);
        const float cn = fg * pcv[c] + ig * gg;
        cp[c] = cn;
        hp[c] = og * fast_tanh(cn);
    }
    *(float4*)(next_h + (size_t)row * Hh + j) = hc;
    *(float4*)(next_c + (size_t)row * Hh + j) = cc;
}

// ---------------------------------------------------------------------------
// Launch
// ---------------------------------------------------------------------------
extern "C" void kernel_launch(void* const* d_in, const int* in_sizes, int n_in,
                              void* d_out, int out_size)
{
    const float* x     = (const float*)d_in[0];
    const float* ph    = (const float*)d_in[1];
    const float* pc    = (const float*)d_in[2];
    const float* Wx    = (const float*)d_in[3];
    const float* Wh    = (const float*)d_in[4];
    const float* bias  = (const float*)d_in[5];
    const float* gamma = (const float*)d_in[6];
    const float* beta  = (const float*)d_in[7];

    float* out    = (float*)d_out;
    float* next_h = out;
    float* next_c = out + (size_t)out_size / 2;

    convert_all_kernel<<<(A_GROUPS + B_GROUPS) / 256, 256>>>(x, ph, Wx, Wh);

    cudaFuncSetAttribute(gemm_mma_kernel,
                         cudaFuncAttributeMaxDynamicSharedMemorySize, SMEM_TOTAL);
    gemm_mma_kernel<<<dim3(FourH / BN, Bsz / BM), GTHREADS, SMEM_TOTAL>>>(bias);

    ln_gates_kernel<<<Bsz, 256>>>(pc, gamma, beta, next_h, next_c);
}